// round 2
// baseline (speedup 1.0000x reference)
#include <cuda_runtime.h>

// GroupWiseContrastiveLoss — factorized:
//   S[i][j] = (sum of clip rows i) . (sum of cap rows j) / (nc[i]*na[j])
//   loss = sum_{i!=j} max(S-diag_i,0) + max(S-diag_j,0)
//
// Inputs (metadata order): im f32[4088*1024], s f32[4091*1024],
//                          num_clips i32[256], num_caps i32[256]
// Output: f32[1]

#define N_VID 256
#define DIM   1024
#define KQ    256   // DIM/4 (float4 chunks)

// scratch (device globals — no allocation allowed)
__device__ float  gA[N_VID * DIM];       // clip segment sums, row-major [i][k]
__device__ float4 gBT4[KQ * N_VID];      // cap segment sums, blocked-transposed [k4][j]
__device__ float  gDiag[N_VID];
__device__ float  gPart[128];

// ---- packed f32x2 helpers -------------------------------------------------
__device__ __forceinline__ void fma2(unsigned long long& acc,
                                     unsigned long long a,
                                     unsigned long long b) {
    asm("fma.rn.f32x2 %0, %1, %2, %0;" : "+l"(acc) : "l"(a), "l"(b));
}
__device__ __forceinline__ float hsum2(unsigned long long v) {
    float lo, hi;
    asm("mov.b64 {%0,%1}, %2;" : "=f"(lo), "=f"(hi) : "l"(v));
    return lo + hi;
}

// ---- K1: segment sums -----------------------------------------------------
// grid 512: blocks [0,256) clips -> gA, [256,512) caps -> gBT4. 256 threads.
__global__ void k_segsum(const float* __restrict__ im,
                         const float* __restrict__ s,
                         const int*  __restrict__ nclips,
                         const int*  __restrict__ ncaps) {
    __shared__ int sc[N_VID];
    const int tid = threadIdx.x;
    const int b   = blockIdx.x;
    const bool isCap = (b >= N_VID);
    const int seg = isCap ? (b - N_VID) : b;
    const int* cnt = isCap ? ncaps : nclips;

    sc[tid] = cnt[tid];
    __syncthreads();
    // inclusive Hillis-Steele scan
    for (int off = 1; off < N_VID; off <<= 1) {
        int v = (tid >= off) ? sc[tid - off] : 0;
        __syncthreads();
        sc[tid] += v;
        __syncthreads();
    }
    const int c     = cnt[seg];
    const int start = sc[seg] - c;

    const float4* p = reinterpret_cast<const float4*>(isCap ? s : im)
                      + (size_t)start * KQ + tid;

    float4 a0 = make_float4(0.f, 0.f, 0.f, 0.f);
    float4 a1 = make_float4(0.f, 0.f, 0.f, 0.f);
    int r = 0;
    for (; r + 1 < c; r += 2) {
        float4 v0 = p[(size_t)r * KQ];
        float4 v1 = p[(size_t)(r + 1) * KQ];
        a0.x += v0.x; a0.y += v0.y; a0.z += v0.z; a0.w += v0.w;
        a1.x += v1.x; a1.y += v1.y; a1.z += v1.z; a1.w += v1.w;
    }
    if (r < c) {
        float4 v0 = p[(size_t)r * KQ];
        a0.x += v0.x; a0.y += v0.y; a0.z += v0.z; a0.w += v0.w;
    }
    float4 acc = make_float4(a0.x + a1.x, a0.y + a1.y, a0.z + a1.z, a0.w + a1.w);

    if (isCap)
        gBT4[tid * N_VID + seg] = acc;                         // [k4][j]
    else
        reinterpret_cast<float4*>(gA)[seg * KQ + tid] = acc;   // row-major
}

// ---- K2: diagonal ---------------------------------------------------------
// grid 256 (one block per video), 128 threads.
__global__ void k_diag(const int* __restrict__ nclips,
                       const int* __restrict__ ncaps) {
    const int i   = blockIdx.x;
    const int tid = threadIdx.x;
    const float4* a = reinterpret_cast<const float4*>(gA) + (size_t)i * KQ;
    float acc = 0.f;
    for (int k4 = tid; k4 < KQ; k4 += 128) {
        float4 av = a[k4];
        float4 bv = gBT4[k4 * N_VID + i];
        acc += av.x * bv.x + av.y * bv.y + av.z * bv.z + av.w * bv.w;
    }
    __shared__ float red[128];
    red[tid] = acc;
    __syncthreads();
    for (int off = 64; off > 0; off >>= 1) {
        if (tid < off) red[tid] += red[tid + off];
        __syncthreads();
    }
    if (tid == 0)
        gDiag[i] = red[0] / ((float)nclips[i] * (float)ncaps[i]);
}

// ---- K3: 256x256x1024 GEMM + fused hinge-loss epilogue --------------------
// grid (4, 32): 4 j-slices of 64 x 32 i-tiles of 8. 256 threads.
// Thread layout: j = j0 + (tid&63); each 64-thread group owns 2 consecutive i.
__global__ __launch_bounds__(256, 2)
void k_gemm_cost(const int* __restrict__ nclips,
                 const int* __restrict__ ncaps) {
    __shared__ float4 sA[8 * KQ];   // 32 KB A-tile
    __shared__ float  sred[256];

    const int tid = threadIdx.x;
    const int i0  = blockIdx.y * 8;
    const int j0  = blockIdx.x * 64;

    // load A tile (8 rows x 1024), coalesced
    const float4* a4 = reinterpret_cast<const float4*>(gA) + (size_t)i0 * KQ;
    for (int t = tid; t < 8 * KQ; t += 256) sA[t] = a4[t];
    __syncthreads();

    const int j  = j0 + (tid & 63);
    const int ig = tid >> 6;           // 0..3
    const int iA = ig * 2;             // local row pair
    const int iB = iA + 1;

    const ulonglong2* bt  = reinterpret_cast<const ulonglong2*>(gBT4);
    const ulonglong2* sa0 = reinterpret_cast<const ulonglong2*>(sA) + iA * KQ;
    const ulonglong2* sa1 = reinterpret_cast<const ulonglong2*>(sA) + iB * KQ;

    unsigned long long acc00 = 0, acc01 = 0, acc10 = 0, acc11 = 0;
    #pragma unroll 4
    for (int k4 = 0; k4 < KQ; ++k4) {
        ulonglong2 bv  = bt[k4 * N_VID + j];   // coalesced LDG.128
        ulonglong2 av0 = sa0[k4];              // broadcast LDS.128
        ulonglong2 av1 = sa1[k4];
        fma2(acc00, av0.x, bv.x);
        fma2(acc01, av0.y, bv.y);
        fma2(acc10, av1.x, bv.x);
        fma2(acc11, av1.y, bv.y);
    }
    const float d0 = hsum2(acc00) + hsum2(acc01);
    const float d1 = hsum2(acc10) + hsum2(acc11);

    const int gi0 = i0 + iA, gi1 = i0 + iB;
    const float ncj = (float)ncaps[j];
    const float S0  = d0 / ((float)nclips[gi0] * ncj);
    const float S1  = d1 / ((float)nclips[gi1] * ncj);
    const float dj  = gDiag[j];

    float contrib = 0.f;
    if (j != gi0) contrib += fmaxf(S0 - gDiag[gi0], 0.f) + fmaxf(S0 - dj, 0.f);
    if (j != gi1) contrib += fmaxf(S1 - gDiag[gi1], 0.f) + fmaxf(S1 - dj, 0.f);

    sred[tid] = contrib;
    __syncthreads();
    for (int off = 128; off > 0; off >>= 1) {
        if (tid < off) sred[tid] += sred[tid + off];
        __syncthreads();
    }
    if (tid == 0)
        gPart[blockIdx.y * gridDim.x + blockIdx.x] = sred[0];
}

// ---- K4: final deterministic reduce --------------------------------------
__global__ void k_final(float* __restrict__ out) {
    const int tid = threadIdx.x;   // 128
    __shared__ float red[128];
    red[tid] = gPart[tid];
    __syncthreads();
    for (int off = 64; off > 0; off >>= 1) {
        if (tid < off) red[tid] += red[tid + off];
        __syncthreads();
    }
    if (tid == 0) out[0] = red[0];
}

extern "C" void kernel_launch(void* const* d_in, const int* in_sizes, int n_in,
                              void* d_out, int out_size) {
    const float* im     = (const float*)d_in[0];
    const float* s      = (const float*)d_in[1];
    const int*   nclips = (const int*)d_in[2];
    const int*   ncaps  = (const int*)d_in[3];
    float*       out    = (float*)d_out;

    k_segsum<<<512, 256>>>(im, s, nclips, ncaps);
    k_diag<<<256, 128>>>(nclips, ncaps);
    dim3 g3(4, 32);
    k_gemm_cost<<<g3, 256>>>(nclips, ncaps);
    k_final<<<1, 128>>>(out);
}